// round 3
// baseline (speedup 1.0000x reference)
#include <cuda_runtime.h>
#include <cstdint>

#define NUM_EXPERTS 8
#define HIDDEN 2048
#define EXPERT_DIM 4096
#define TOKENS 1024

// Gated activations scratch [E, T, I] fp32
__device__ float g_act[(size_t)NUM_EXPERTS * TOKENS * EXPERT_DIM];

__device__ __forceinline__ uint32_t f2tf32(float x) {
    uint32_t r;
    asm("cvt.rna.tf32.f32 %0, %1;" : "=r"(r) : "f"(x));
    return r;
}

__device__ __forceinline__ void mma_tf32(float* c, const uint32_t* a, const uint32_t* b) {
    asm volatile(
        "mma.sync.aligned.m16n8k8.row.col.f32.tf32.tf32.f32 "
        "{%0,%1,%2,%3}, {%4,%5,%6,%7}, {%8,%9}, {%0,%1,%2,%3};\n"
        : "+f"(c[0]), "+f"(c[1]), "+f"(c[2]), "+f"(c[3])
        : "r"(a[0]), "r"(a[1]), "r"(a[2]), "r"(a[3]), "r"(b[0]), "r"(b[1]));
}

// Shared layouts (dynamic smem):
//   As[2][128][20]   (stride 20: frag loads conflict-free)
//   Bs[2][16][264]   (stride 264: 264%32==8 -> rows k8+tg spread {0,8,16,24}+g)
#define A_STRIDE 20
#define B_STRIDE 264
#define A_WORDS (2 * 128 * A_STRIDE)
#define B_WORDS (2 * 16 * B_STRIDE)
#define SMEM_BYTES ((A_WORDS + B_WORDS) * 4)

// ---------------------------------------------------------------------------
// GEMM1 + silu. Block: 128 tokens x 128 gated cols. K = HIDDEN = 2048, BK=16.
// 8 warps = 2 (M) x 4 (N). Warp tile: 64 x 32 for BOTH gate and up
// (A fragments shared across the two B sets -> 16 FLOP / LDS byte).
// B smem: cols 0..127 = gate (n0..), cols 128..255 = up (n0+4096..).
// ---------------------------------------------------------------------------
__global__ __launch_bounds__(256, 1) void gemm1_kernel(
    const float* __restrict__ X,    // [E*T, H]
    const float* __restrict__ W1)   // [E, H, 2I]
{
    extern __shared__ uint32_t sm[];
    uint32_t (*As)[128][A_STRIDE] = (uint32_t(*)[128][A_STRIDE])sm;
    uint32_t (*Bs)[16][B_STRIDE]  = (uint32_t(*)[16][B_STRIDE])(sm + A_WORDS);

    const int e  = blockIdx.z;
    const int m0 = blockIdx.y * 128;
    const int n0 = blockIdx.x * 128;

    const int tid  = threadIdx.x;
    const int warp = tid >> 5;
    const int lane = tid & 31;
    const int wm = (warp >> 2) * 64;   // 2 warps in M
    const int wn = (warp & 3) * 32;    // 4 warps in N
    const int g  = lane >> 2;
    const int tg = lane & 3;

    const float* Ap = X + (size_t)(e * TOKENS + m0) * HIDDEN;
    const float* Bp = W1 + (size_t)e * HIDDEN * (2 * EXPERT_DIM);

    // Staging maps
    const int s_arow = tid >> 2;          // A: 0..63 (x2 via i)
    const int s_akq  = (tid & 3) * 4;     // A: word col 0,4,8,12
    // B: 1024 float4 per tile; idx = tid + i*256; c4 = idx&63 -> col = 4*c4; k = idx>>6

    float4 ra[2];
    float4 rb[4];

    // ---- prologue: stage tile 0
    {
        #pragma unroll
        for (int i = 0; i < 2; ++i) {
            const int row = s_arow + i * 64;
            float4 v = *(const float4*)(Ap + (size_t)row * HIDDEN + s_akq);
            As[0][row][s_akq + 0] = f2tf32(v.x);
            As[0][row][s_akq + 1] = f2tf32(v.y);
            As[0][row][s_akq + 2] = f2tf32(v.z);
            As[0][row][s_akq + 3] = f2tf32(v.w);
        }
        #pragma unroll
        for (int i = 0; i < 4; ++i) {
            const int idx = tid + i * 256;
            const int c = (idx & 63) * 4;
            const int k = idx >> 6;
            const int gcol = n0 + (c < 128 ? c : 4096 + (c - 128));
            float4 v = *(const float4*)(Bp + (size_t)k * (2 * EXPERT_DIM) + gcol);
            Bs[0][k][c + 0] = f2tf32(v.x);
            Bs[0][k][c + 1] = f2tf32(v.y);
            Bs[0][k][c + 2] = f2tf32(v.z);
            Bs[0][k][c + 3] = f2tf32(v.w);
        }
    }
    __syncthreads();

    float accg[4][4][4] = {};
    float accu[4][4][4] = {};

    const int nT = HIDDEN / 16;  // 128
    #pragma unroll 1
    for (int kt = 0; kt < nT; ++kt) {
        const int buf = kt & 1;
        if (kt + 1 < nT) {
            const float* a = Ap + (kt + 1) * 16;
            #pragma unroll
            for (int i = 0; i < 2; ++i)
                ra[i] = *(const float4*)(a + (size_t)(s_arow + i * 64) * HIDDEN + s_akq);
            #pragma unroll
            for (int i = 0; i < 4; ++i) {
                const int idx = tid + i * 256;
                const int c = (idx & 63) * 4;
                const int k = (kt + 1) * 16 + (idx >> 6);
                const int gcol = n0 + (c < 128 ? c : 4096 + (c - 128));
                rb[i] = *(const float4*)(Bp + (size_t)k * (2 * EXPERT_DIM) + gcol);
            }
        }

        #pragma unroll
        for (int ks = 0; ks < 2; ++ks) {
            const int k8 = ks * 8;
            uint32_t af[4][4];
            #pragma unroll
            for (int im = 0; im < 4; ++im) {
                const int r = wm + im * 16 + g;
                af[im][0] = As[buf][r][k8 + tg];
                af[im][1] = As[buf][r + 8][k8 + tg];
                af[im][2] = As[buf][r][k8 + tg + 4];
                af[im][3] = As[buf][r + 8][k8 + tg + 4];
            }
            uint32_t bg[4][2], bu[4][2];
            #pragma unroll
            for (int in = 0; in < 4; ++in) {
                const int c = wn + in * 8 + g;
                bg[in][0] = Bs[buf][k8 + tg][c];
                bg[in][1] = Bs[buf][k8 + tg + 4][c];
                bu[in][0] = Bs[buf][k8 + tg][c + 128];
                bu[in][1] = Bs[buf][k8 + tg + 4][c + 128];
            }
            #pragma unroll
            for (int im = 0; im < 4; ++im) {
                #pragma unroll
                for (int in = 0; in < 4; ++in) {
                    mma_tf32(accg[im][in], af[im], bg[in]);
                    mma_tf32(accu[im][in], af[im], bu[in]);
                }
            }
        }

        if (kt + 1 < nT) {
            const int nb = (kt + 1) & 1;
            #pragma unroll
            for (int i = 0; i < 2; ++i) {
                const int row = s_arow + i * 64;
                As[nb][row][s_akq + 0] = f2tf32(ra[i].x);
                As[nb][row][s_akq + 1] = f2tf32(ra[i].y);
                As[nb][row][s_akq + 2] = f2tf32(ra[i].z);
                As[nb][row][s_akq + 3] = f2tf32(ra[i].w);
            }
            #pragma unroll
            for (int i = 0; i < 4; ++i) {
                const int idx = tid + i * 256;
                const int c = (idx & 63) * 4;
                const int k = idx >> 6;
                Bs[nb][k][c + 0] = f2tf32(rb[i].x);
                Bs[nb][k][c + 1] = f2tf32(rb[i].y);
                Bs[nb][k][c + 2] = f2tf32(rb[i].z);
                Bs[nb][k][c + 3] = f2tf32(rb[i].w);
            }
        }
        __syncthreads();
    }

    // Epilogue: gated = up * silu(gate) -> g_act
    float* Gout = g_act + (size_t)e * TOKENS * EXPERT_DIM;
    #pragma unroll
    for (int im = 0; im < 4; ++im) {
        #pragma unroll
        for (int in = 0; in < 4; ++in) {
            #pragma unroll
            for (int h = 0; h < 2; ++h) {
                const int r = m0 + wm + im * 16 + g + h * 8;
                const int c = n0 + wn + in * 8 + 2 * tg;
                const float gv0 = accg[im][in][h * 2 + 0];
                const float gv1 = accg[im][in][h * 2 + 1];
                const float uv0 = accu[im][in][h * 2 + 0];
                const float uv1 = accu[im][in][h * 2 + 1];
                const float s0 = gv0 / (1.0f + __expf(-gv0));
                const float s1 = gv1 / (1.0f + __expf(-gv1));
                *(float2*)(Gout + (size_t)r * EXPERT_DIM + c) = make_float2(uv0 * s0, uv1 * s1);
            }
        }
    }
}

// ---------------------------------------------------------------------------
// GEMM2: Out[e] = G[e] (1024x4096) @ W2[e] (4096x2048).
// Block: 128 x 256, BK=16. 8 warps = 2 (M) x 4 (N). Warp tile 64 x 64.
// ---------------------------------------------------------------------------
__global__ __launch_bounds__(256, 1) void gemm2_kernel(
    const float* __restrict__ W2,   // [E, I, H]
    float* __restrict__ Out)        // [E*T, H]
{
    extern __shared__ uint32_t sm[];
    uint32_t (*As)[128][A_STRIDE] = (uint32_t(*)[128][A_STRIDE])sm;
    uint32_t (*Bs)[16][B_STRIDE]  = (uint32_t(*)[16][B_STRIDE])(sm + A_WORDS);

    const int e  = blockIdx.z;
    const int m0 = blockIdx.y * 128;
    const int n0 = blockIdx.x * 256;

    const int tid  = threadIdx.x;
    const int warp = tid >> 5;
    const int lane = tid & 31;
    const int wm = (warp >> 2) * 64;   // 2 warps in M
    const int wn = (warp & 3) * 64;    // 4 warps in N
    const int g  = lane >> 2;
    const int tg = lane & 3;

    const float* Ap = g_act + (size_t)e * TOKENS * EXPERT_DIM + (size_t)m0 * EXPERT_DIM;
    const float* Bp = W2 + (size_t)e * EXPERT_DIM * HIDDEN + n0;

    const int s_arow = tid >> 2;
    const int s_akq  = (tid & 3) * 4;

    float4 ra[2];
    float4 rb[4];

    {
        #pragma unroll
        for (int i = 0; i < 2; ++i) {
            const int row = s_arow + i * 64;
            float4 v = *(const float4*)(Ap + (size_t)row * EXPERT_DIM + s_akq);
            As[0][row][s_akq + 0] = f2tf32(v.x);
            As[0][row][s_akq + 1] = f2tf32(v.y);
            As[0][row][s_akq + 2] = f2tf32(v.z);
            As[0][row][s_akq + 3] = f2tf32(v.w);
        }
        #pragma unroll
        for (int i = 0; i < 4; ++i) {
            const int idx = tid + i * 256;
            const int c = (idx & 63) * 4;
            const int k = idx >> 6;
            float4 v = *(const float4*)(Bp + (size_t)k * HIDDEN + c);
            Bs[0][k][c + 0] = f2tf32(v.x);
            Bs[0][k][c + 1] = f2tf32(v.y);
            Bs[0][k][c + 2] = f2tf32(v.z);
            Bs[0][k][c + 3] = f2tf32(v.w);
        }
    }
    __syncthreads();

    float acc[4][8][4] = {};

    const int nT = EXPERT_DIM / 16;  // 256
    #pragma unroll 1
    for (int kt = 0; kt < nT; ++kt) {
        const int buf = kt & 1;
        if (kt + 1 < nT) {
            const float* a = Ap + (kt + 1) * 16;
            #pragma unroll
            for (int i = 0; i < 2; ++i)
                ra[i] = *(const float4*)(a + (size_t)(s_arow + i * 64) * EXPERT_DIM + s_akq);
            #pragma unroll
            for (int i = 0; i < 4; ++i) {
                const int idx = tid + i * 256;
                const int c = (idx & 63) * 4;
                const int k = (kt + 1) * 16 + (idx >> 6);
                rb[i] = *(const float4*)(Bp + (size_t)k * HIDDEN + c);
            }
        }

        #pragma unroll
        for (int ks = 0; ks < 2; ++ks) {
            const int k8 = ks * 8;
            uint32_t af[4][4];
            #pragma unroll
            for (int im = 0; im < 4; ++im) {
                const int r = wm + im * 16 + g;
                af[im][0] = As[buf][r][k8 + tg];
                af[im][1] = As[buf][r + 8][k8 + tg];
                af[im][2] = As[buf][r][k8 + tg + 4];
                af[im][3] = As[buf][r + 8][k8 + tg + 4];
            }
            uint32_t bf[8][2];
            #pragma unroll
            for (int in = 0; in < 8; ++in) {
                const int c = wn + in * 8 + g;
                bf[in][0] = Bs[buf][k8 + tg][c];
                bf[in][1] = Bs[buf][k8 + tg + 4][c];
            }
            #pragma unroll
            for (int im = 0; im < 4; ++im) {
                #pragma unroll
                for (int in = 0; in < 8; ++in) {
                    mma_tf32(acc[im][in], af[im], bf[in]);
                }
            }
        }

        if (kt + 1 < nT) {
            const int nb = (kt + 1) & 1;
            #pragma unroll
            for (int i = 0; i < 2; ++i) {
                const int row = s_arow + i * 64;
                As[nb][row][s_akq + 0] = f2tf32(ra[i].x);
                As[nb][row][s_akq + 1] = f2tf32(ra[i].y);
                As[nb][row][s_akq + 2] = f2tf32(ra[i].z);
                As[nb][row][s_akq + 3] = f2tf32(ra[i].w);
            }
            #pragma unroll
            for (int i = 0; i < 4; ++i) {
                const int idx = tid + i * 256;
                const int c = (idx & 63) * 4;
                const int k = idx >> 6;
                Bs[nb][k][c + 0] = f2tf32(rb[i].x);
                Bs[nb][k][c + 1] = f2tf32(rb[i].y);
                Bs[nb][k][c + 2] = f2tf32(rb[i].z);
                Bs[nb][k][c + 3] = f2tf32(rb[i].w);
            }
        }
        __syncthreads();
    }

    float* Optr = Out + (size_t)(e * TOKENS + m0) * HIDDEN + n0;
    #pragma unroll
    for (int im = 0; im < 4; ++im) {
        #pragma unroll
        for (int in = 0; in < 8; ++in) {
            #pragma unroll
            for (int h = 0; h < 2; ++h) {
                const int r = wm + im * 16 + g + h * 8;
                const int c = wn + in * 8 + 2 * tg;
                *(float2*)(Optr + (size_t)r * HIDDEN + c) =
                    make_float2(acc[im][in][h * 2 + 0], acc[im][in][h * 2 + 1]);
            }
        }
    }
}

extern "C" void kernel_launch(void* const* d_in, const int* in_sizes, int n_in,
                              void* d_out, int out_size) {
    const float* X  = (const float*)d_in[0];   // hidden_states [8192, 2048]
    const float* W1 = (const float*)d_in[1];   // gate_up_proj  [8, 2048, 8192]
    const float* W2 = (const float*)d_in[2];   // down_proj     [8, 4096, 2048]
    float* Out = (float*)d_out;                // [8192, 2048]

    static int attr_done = 0;
    if (!attr_done) {
        cudaFuncSetAttribute(gemm1_kernel, cudaFuncAttributeMaxDynamicSharedMemorySize, SMEM_BYTES);
        cudaFuncSetAttribute(gemm2_kernel, cudaFuncAttributeMaxDynamicSharedMemorySize, SMEM_BYTES);
        attr_done = 1;
    }

    dim3 blk(256);
    dim3 g1(EXPERT_DIM / 128, TOKENS / 128, NUM_EXPERTS);  // 32 x 8 x 8
    dim3 g2(HIDDEN / 256, TOKENS / 128, NUM_EXPERTS);      // 8 x 8 x 8
    gemm1_kernel<<<g1, blk, SMEM_BYTES>>>(X, W1);
    gemm2_kernel<<<g2, blk, SMEM_BYTES>>>(W2, Out);
}

// round 4
// speedup vs baseline: 1.1306x; 1.1306x over previous
#include <cuda_runtime.h>
#include <cstdint>

#define NUM_EXPERTS 8
#define HIDDEN 2048
#define EXPERT_DIM 4096
#define TOKENS 1024

// Gated activations scratch [E, T, I] fp32
__device__ float g_act[(size_t)NUM_EXPERTS * TOKENS * EXPERT_DIM];

// pack two fp32 -> one fp16x2 word: lo = a (even k), hi = b (odd k)
__device__ __forceinline__ uint32_t pack_h2(float a, float b) {
    uint32_t r;
    asm("cvt.rn.f16x2.f32 %0, %1, %2;" : "=r"(r) : "f"(b), "f"(a));
    return r;
}

// D += A*B, m16n8k16 fp16 operands, fp32 accumulate
__device__ __forceinline__ void mma_f16(float* c, const uint32_t* a, const uint32_t* b) {
    asm volatile(
        "mma.sync.aligned.m16n8k16.row.col.f32.f16.f16.f32 "
        "{%0,%1,%2,%3}, {%4,%5,%6,%7}, {%8,%9}, {%0,%1,%2,%3};\n"
        : "+f"(c[0]), "+f"(c[1]), "+f"(c[2]), "+f"(c[3])
        : "r"(a[0]), "r"(a[1]), "r"(a[2]), "r"(a[3]), "r"(b[0]), "r"(b[1]));
}

// Smem strides (in 32-bit words). Both ≡ 4 (mod 32) so fragment loads across
// (g in rows/cols, tg in k-pairs) hit 32 distinct banks.
#define A_ST 12   // As[row 0..127][k-pair 0..7 (+pad)]
#define B_ST 12   // Bs[n 0..255][k-pair 0..7 (+pad)], XOR-swizzled word index

// ---------------------------------------------------------------------------
// GEMM1 + silu. Block: 128 tokens x 128 gated cols. K = 2048, BK = 16.
// 8 warps = 2(M) x 4(N). Warp tile 64 x 32 for BOTH gate and up (A frags
// shared). B smem rows: n 0..127 = gate (n0+n), 128..255 = up (n0+4096+n-128).
// ---------------------------------------------------------------------------
__global__ __launch_bounds__(256, 1) void gemm1_kernel(
    const float* __restrict__ X,    // [E*T, H]
    const float* __restrict__ W1)   // [E, H, 2I]
{
    __shared__ uint32_t As[2][128][A_ST];
    __shared__ uint32_t Bs[2][256][B_ST];

    const int e  = blockIdx.z;
    const int m0 = blockIdx.y * 128;
    const int n0 = blockIdx.x * 128;

    const int tid  = threadIdx.x;
    const int warp = tid >> 5;
    const int lane = tid & 31;
    const int wm = (warp >> 2) * 64;   // 2 warps in M
    const int wn = (warp & 3) * 32;    // 4 warps in N
    const int g  = lane >> 2;
    const int tg = lane & 3;

    const float* Ap = X + (size_t)(e * TOKENS + m0) * HIDDEN;
    const float* Bp = W1 + (size_t)e * HIDDEN * (2 * EXPERT_DIM);
    const int LDB = 2 * EXPERT_DIM;

    // A staging: 512 float4 units (128 rows x 4) -> 2/thread
    const int a_row0 = tid >> 2;          // unit0 row (unit1 row = +64)
    const int a_u    = tid & 3;           // float4 index in row (k = 4u..4u+3)
    // B staging: 1024 units (256 n x 4 kq) -> 4/thread
    //   idx = tid + i*256: n = idx & 255, kq = idx >> 8

    float4 ra[2];
    float rbx[4][4];

    // prologue: stage tile 0
    {
        #pragma unroll
        for (int i = 0; i < 2; ++i) {
            const int row = a_row0 + i * 64;
            float4 v = *(const float4*)(Ap + (size_t)row * HIDDEN + a_u * 4);
            As[0][row][a_u * 2 + 0] = pack_h2(v.x, v.y);
            As[0][row][a_u * 2 + 1] = pack_h2(v.z, v.w);
        }
        #pragma unroll
        for (int i = 0; i < 4; ++i) {
            const int idx = tid + i * 256;
            const int n = idx & 255, kq = idx >> 8;
            const int gcol = n0 + (n < 128 ? n : 4096 + (n - 128));
            const float* p = Bp + (size_t)(kq * 4) * LDB + gcol;
            const uint32_t w0 = pack_h2(p[0], p[LDB]);
            const uint32_t w1 = pack_h2(p[2 * LDB], p[3 * LDB]);
            const int woff = (2 * kq) ^ (((n >> 3) & 3) << 1);
            *(uint2*)&Bs[0][n][woff] = make_uint2(w0, w1);
        }
    }
    __syncthreads();

    float accg[4][4][4] = {};
    float accu[4][4][4] = {};

    const int nT = HIDDEN / 16;  // 128
    #pragma unroll 1
    for (int kt = 0; kt < nT; ++kt) {
        const int buf = kt & 1;
        if (kt + 1 < nT) {
            const float* a = Ap + (kt + 1) * 16;
            #pragma unroll
            for (int i = 0; i < 2; ++i)
                ra[i] = *(const float4*)(a + (size_t)(a_row0 + i * 64) * HIDDEN + a_u * 4);
            #pragma unroll
            for (int i = 0; i < 4; ++i) {
                const int idx = tid + i * 256;
                const int n = idx & 255, kq = idx >> 8;
                const int gcol = n0 + (n < 128 ? n : 4096 + (n - 128));
                const float* p = Bp + (size_t)((kt + 1) * 16 + kq * 4) * LDB + gcol;
                rbx[i][0] = p[0];
                rbx[i][1] = p[LDB];
                rbx[i][2] = p[2 * LDB];
                rbx[i][3] = p[3 * LDB];
            }
        }

        // one k16 MMA step
        {
            uint32_t af[4][4];
            #pragma unroll
            for (int im = 0; im < 4; ++im) {
                const int r = wm + im * 16 + g;
                af[im][0] = As[buf][r][tg];
                af[im][1] = As[buf][r + 8][tg];
                af[im][2] = As[buf][r][tg + 4];
                af[im][3] = As[buf][r + 8][tg + 4];
            }
            uint32_t bg[4][2], bu[4][2];
            #pragma unroll
            for (int in = 0; in < 4; ++in) {
                const int cg = wn + in * 8 + g;
                const int cu = cg + 128;
                const int wg0 = tg ^ (((cg >> 3) & 3) << 1);
                const int wu0 = tg ^ (((cu >> 3) & 3) << 1);
                bg[in][0] = Bs[buf][cg][wg0];
                bg[in][1] = Bs[buf][cg][wg0 ^ 4];
                bu[in][0] = Bs[buf][cu][wu0];
                bu[in][1] = Bs[buf][cu][wu0 ^ 4];
            }
            #pragma unroll
            for (int im = 0; im < 4; ++im) {
                #pragma unroll
                for (int in = 0; in < 4; ++in) {
                    mma_f16(accg[im][in], af[im], bg[in]);
                    mma_f16(accu[im][in], af[im], bu[in]);
                }
            }
        }

        if (kt + 1 < nT) {
            const int nb = (kt + 1) & 1;
            #pragma unroll
            for (int i = 0; i < 2; ++i) {
                const int row = a_row0 + i * 64;
                As[nb][row][a_u * 2 + 0] = pack_h2(ra[i].x, ra[i].y);
                As[nb][row][a_u * 2 + 1] = pack_h2(ra[i].z, ra[i].w);
            }
            #pragma unroll
            for (int i = 0; i < 4; ++i) {
                const int idx = tid + i * 256;
                const int n = idx & 255, kq = idx >> 8;
                const uint32_t w0 = pack_h2(rbx[i][0], rbx[i][1]);
                const uint32_t w1 = pack_h2(rbx[i][2], rbx[i][3]);
                const int woff = (2 * kq) ^ (((n >> 3) & 3) << 1);
                *(uint2*)&Bs[nb][n][woff] = make_uint2(w0, w1);
            }
        }
        __syncthreads();
    }

    // Epilogue: gated = up * silu(gate) -> g_act
    float* Gout = g_act + (size_t)e * TOKENS * EXPERT_DIM;
    #pragma unroll
    for (int im = 0; im < 4; ++im) {
        #pragma unroll
        for (int in = 0; in < 4; ++in) {
            #pragma unroll
            for (int h = 0; h < 2; ++h) {
                const int r = m0 + wm + im * 16 + g + h * 8;
                const int c = n0 + wn + in * 8 + 2 * tg;
                const float gv0 = accg[im][in][h * 2 + 0];
                const float gv1 = accg[im][in][h * 2 + 1];
                const float uv0 = accu[im][in][h * 2 + 0];
                const float uv1 = accu[im][in][h * 2 + 1];
                const float s0 = gv0 / (1.0f + __expf(-gv0));
                const float s1 = gv1 / (1.0f + __expf(-gv1));
                *(float2*)(Gout + (size_t)r * EXPERT_DIM + c) = make_float2(uv0 * s0, uv1 * s1);
            }
        }
    }
}

// ---------------------------------------------------------------------------
// GEMM2: Out[e] = G[e] (1024x4096) @ W2[e] (4096x2048).
// Block: 128 x 256, BK = 16. 8 warps = 2(M) x 4(N). Warp tile 64 x 64.
// ---------------------------------------------------------------------------
__global__ __launch_bounds__(256, 1) void gemm2_kernel(
    const float* __restrict__ W2,   // [E, I, H]
    float* __restrict__ Out)        // [E*T, H]
{
    __shared__ uint32_t As[2][128][A_ST];
    __shared__ uint32_t Bs[2][256][B_ST];

    const int e  = blockIdx.z;
    const int m0 = blockIdx.y * 128;
    const int n0 = blockIdx.x * 256;

    const int tid  = threadIdx.x;
    const int warp = tid >> 5;
    const int lane = tid & 31;
    const int wm = (warp >> 2) * 64;   // 2 warps in M
    const int wn = (warp & 3) * 64;    // 4 warps in N
    const int g  = lane >> 2;
    const int tg = lane & 3;

    const float* Ap = g_act + (size_t)e * TOKENS * EXPERT_DIM + (size_t)m0 * EXPERT_DIM;
    const float* Bp = W2 + (size_t)e * EXPERT_DIM * HIDDEN + n0;
    const int LDB = HIDDEN;

    const int a_row0 = tid >> 2;
    const int a_u    = tid & 3;

    float4 ra[2];
    float rbx[4][4];

    {
        #pragma unroll
        for (int i = 0; i < 2; ++i) {
            const int row = a_row0 + i * 64;
            float4 v = *(const float4*)(Ap + (size_t)row * EXPERT_DIM + a_u * 4);
            As[0][row][a_u * 2 + 0] = pack_h2(v.x, v.y);
            As[0][row][a_u * 2 + 1] = pack_h2(v.z, v.w);
        }
        #pragma unroll
        for (int i = 0; i < 4; ++i) {
            const int idx = tid + i * 256;
            const int n = idx & 255, kq = idx >> 8;
            const float* p = Bp + (size_t)(kq * 4) * LDB + n;
            const uint32_t w0 = pack_h2(p[0], p[LDB]);
            const uint32_t w1 = pack_h2(p[2 * LDB], p[3 * LDB]);
            const int woff = (2 * kq) ^ (((n >> 3) & 3) << 1);
            *(uint2*)&Bs[0][n][woff] = make_uint2(w0, w1);
        }
    }
    __syncthreads();

    float acc[4][8][4] = {};

    const int nT = EXPERT_DIM / 16;  // 256
    #pragma unroll 1
    for (int kt = 0; kt < nT; ++kt) {
        const int buf = kt & 1;
        if (kt + 1 < nT) {
            const float* a = Ap + (kt + 1) * 16;
            #pragma unroll
            for (int i = 0; i < 2; ++i)
                ra[i] = *(const float4*)(a + (size_t)(a_row0 + i * 64) * EXPERT_DIM + a_u * 4);
            #pragma unroll
            for (int i = 0; i < 4; ++i) {
                const int idx = tid + i * 256;
                const int n = idx & 255, kq = idx >> 8;
                const float* p = Bp + (size_t)((kt + 1) * 16 + kq * 4) * LDB + n;
                rbx[i][0] = p[0];
                rbx[i][1] = p[LDB];
                rbx[i][2] = p[2 * LDB];
                rbx[i][3] = p[3 * LDB];
            }
        }

        {
            uint32_t af[4][4];
            #pragma unroll
            for (int im = 0; im < 4; ++im) {
                const int r = wm + im * 16 + g;
                af[im][0] = As[buf][r][tg];
                af[im][1] = As[buf][r + 8][tg];
                af[im][2] = As[buf][r][tg + 4];
                af[im][3] = As[buf][r + 8][tg + 4];
            }
            uint32_t bf[8][2];
            #pragma unroll
            for (int in = 0; in < 8; ++in) {
                const int c = wn + in * 8 + g;
                const int w0 = tg ^ (((c >> 3) & 3) << 1);
                bf[in][0] = Bs[buf][c][w0];
                bf[in][1] = Bs[buf][c][w0 ^ 4];
            }
            #pragma unroll
            for (int im = 0; im < 4; ++im) {
                #pragma unroll
                for (int in = 0; in < 8; ++in) {
                    mma_f16(acc[im][in], af[im], bf[in]);
                }
            }
        }

        if (kt + 1 < nT) {
            const int nb = (kt + 1) & 1;
            #pragma unroll
            for (int i = 0; i < 2; ++i) {
                const int row = a_row0 + i * 64;
                As[nb][row][a_u * 2 + 0] = pack_h2(ra[i].x, ra[i].y);
                As[nb][row][a_u * 2 + 1] = pack_h2(ra[i].z, ra[i].w);
            }
            #pragma unroll
            for (int i = 0; i < 4; ++i) {
                const int idx = tid + i * 256;
                const int n = idx & 255, kq = idx >> 8;
                const uint32_t w0 = pack_h2(rbx[i][0], rbx[i][1]);
                const uint32_t w1 = pack_h2(rbx[i][2], rbx[i][3]);
                const int woff = (2 * kq) ^ (((n >> 3) & 3) << 1);
                *(uint2*)&Bs[nb][n][woff] = make_uint2(w0, w1);
            }
        }
        __syncthreads();
    }

    float* Optr = Out + (size_t)(e * TOKENS + m0) * HIDDEN + n0;
    #pragma unroll
    for (int im = 0; im < 4; ++im) {
        #pragma unroll
        for (int in = 0; in < 8; ++in) {
            #pragma unroll
            for (int h = 0; h < 2; ++h) {
                const int r = wm + im * 16 + g + h * 8;
                const int c = wn + in * 8 + 2 * tg;
                *(float2*)(Optr + (size_t)r * HIDDEN + c) =
                    make_float2(acc[im][in][h * 2 + 0], acc[im][in][h * 2 + 1]);
            }
        }
    }
}

extern "C" void kernel_launch(void* const* d_in, const int* in_sizes, int n_in,
                              void* d_out, int out_size) {
    const float* X  = (const float*)d_in[0];   // hidden_states [8192, 2048]
    const float* W1 = (const float*)d_in[1];   // gate_up_proj  [8, 2048, 8192]
    const float* W2 = (const float*)d_in[2];   // down_proj     [8, 4096, 2048]
    float* Out = (float*)d_out;                // [8192, 2048]

    dim3 blk(256);
    dim3 g1(EXPERT_DIM / 128, TOKENS / 128, NUM_EXPERTS);  // 32 x 8 x 8
    dim3 g2(HIDDEN / 256, TOKENS / 128, NUM_EXPERTS);      // 8 x 8 x 8
    gemm1_kernel<<<g1, blk>>>(X, W1);
    gemm2_kernel<<<g2, blk>>>(W2, Out);
}

// round 5
// speedup vs baseline: 1.3923x; 1.2314x over previous
#include <cuda_runtime.h>
#include <cstdint>

#define NUM_EXPERTS 8
#define HIDDEN 2048
#define EXPERT_DIM 4096
#define TOKENS 1024

// Gated activations scratch [E, T, I] fp32
__device__ float g_act[(size_t)NUM_EXPERTS * TOKENS * EXPERT_DIM];

// pack two fp32 -> one fp16x2 word: lo = a (even k), hi = b (odd k)
__device__ __forceinline__ uint32_t pack_h2(float a, float b) {
    uint32_t r;
    asm("cvt.rn.f16x2.f32 %0, %1, %2;" : "=r"(r) : "f"(b), "f"(a));
    return r;
}

// D += A*B, m16n8k16 fp16 operands, fp32 accumulate
__device__ __forceinline__ void mma_f16(float* c, const uint32_t* a, const uint32_t* b) {
    asm volatile(
        "mma.sync.aligned.m16n8k16.row.col.f32.f16.f16.f32 "
        "{%0,%1,%2,%3}, {%4,%5,%6,%7}, {%8,%9}, {%0,%1,%2,%3};\n"
        : "+f"(c[0]), "+f"(c[1]), "+f"(c[2]), "+f"(c[3])
        : "r"(a[0]), "r"(a[1]), "r"(a[2]), "r"(a[3]), "r"(b[0]), "r"(b[1]));
}

// Strides in 32-bit words; both ≡ 12 (mod 32) -> fragment loads across
// (g, tg) hit 32 distinct banks (verified round 4).
#define A_ST 12   // As[row][k-pair word 0..7 (+pad)]
#define B_ST 12   // Bs[n][k-pair word, XOR-swizzled]

// ---------------------------------------------------------------------------
// GEMM1 + silu. Block: 128 tokens x 64 gated cols (gate+up = 128 B rows).
// K = 2048, BK = 16. 8 warps = 4(M) x 2(N). Warp tile 32 x 32 dual.
// 2 CTAs / SM.
// ---------------------------------------------------------------------------
__global__ __launch_bounds__(256, 2) void gemm1_kernel(
    const float* __restrict__ X,    // [E*T, H]
    const float* __restrict__ W1)   // [E, H, 2I]
{
    __shared__ uint32_t As[2][128][A_ST];
    __shared__ uint32_t Bs[2][128][B_ST];

    const int e  = blockIdx.z;
    const int m0 = blockIdx.y * 128;
    const int n0 = blockIdx.x * 64;

    const int tid  = threadIdx.x;
    const int warp = tid >> 5;
    const int lane = tid & 31;
    const int wm = (warp >> 1) * 32;   // 4 warps in M
    const int wn = (warp & 1) * 32;    // 2 warps in N
    const int g  = lane >> 2;
    const int tg = lane & 3;

    const float* Ap = X + (size_t)(e * TOKENS + m0) * HIDDEN;
    const float* Bp = W1 + (size_t)e * HIDDEN * (2 * EXPERT_DIM);
    const int LDB = 2 * EXPERT_DIM;

    const int a_row0 = tid >> 2;       // 0..63 (+64)
    const int a_u    = tid & 3;        // float4 index in k16 row

    float4 ra[2];
    float rbx[2][4];

    // prologue
    {
        #pragma unroll
        for (int i = 0; i < 2; ++i) {
            const int row = a_row0 + i * 64;
            float4 v = *(const float4*)(Ap + (size_t)row * HIDDEN + a_u * 4);
            As[0][row][a_u * 2 + 0] = pack_h2(v.x, v.y);
            As[0][row][a_u * 2 + 1] = pack_h2(v.z, v.w);
        }
        #pragma unroll
        for (int i = 0; i < 2; ++i) {
            const int idx = tid + i * 256;       // 0..511
            const int n = idx & 127, kq = idx >> 7;
            const int gcol = n0 + (n < 64 ? n : 4096 + (n - 64));
            const float* p = Bp + (size_t)(kq * 4) * LDB + gcol;
            const uint32_t w0 = pack_h2(p[0], p[LDB]);
            const uint32_t w1 = pack_h2(p[2 * LDB], p[3 * LDB]);
            const int woff = (2 * kq) ^ (((n >> 3) & 3) << 1);
            *(uint2*)&Bs[0][n][woff] = make_uint2(w0, w1);
        }
    }
    __syncthreads();

    float accg[2][4][4] = {};
    float accu[2][4][4] = {};

    const int nT = HIDDEN / 16;  // 128
    #pragma unroll 1
    for (int kt = 0; kt < nT; ++kt) {
        const int buf = kt & 1;
        if (kt + 1 < nT) {
            const float* a = Ap + (kt + 1) * 16;
            #pragma unroll
            for (int i = 0; i < 2; ++i)
                ra[i] = *(const float4*)(a + (size_t)(a_row0 + i * 64) * HIDDEN + a_u * 4);
            #pragma unroll
            for (int i = 0; i < 2; ++i) {
                const int idx = tid + i * 256;
                const int n = idx & 127, kq = idx >> 7;
                const int gcol = n0 + (n < 64 ? n : 4096 + (n - 64));
                const float* p = Bp + (size_t)((kt + 1) * 16 + kq * 4) * LDB + gcol;
                rbx[i][0] = p[0];
                rbx[i][1] = p[LDB];
                rbx[i][2] = p[2 * LDB];
                rbx[i][3] = p[3 * LDB];
            }
        }

        {
            uint32_t af[2][4];
            #pragma unroll
            for (int im = 0; im < 2; ++im) {
                const int r = wm + im * 16 + g;
                af[im][0] = As[buf][r][tg];
                af[im][1] = As[buf][r + 8][tg];
                af[im][2] = As[buf][r][tg + 4];
                af[im][3] = As[buf][r + 8][tg + 4];
            }
            uint32_t bg[4][2], bu[4][2];
            #pragma unroll
            for (int in = 0; in < 4; ++in) {
                const int cg = wn + in * 8 + g;
                const int cu = cg + 64;
                const int wg0 = tg ^ (((cg >> 3) & 3) << 1);
                const int wu0 = tg ^ (((cu >> 3) & 3) << 1);
                bg[in][0] = Bs[buf][cg][wg0];
                bg[in][1] = Bs[buf][cg][wg0 ^ 4];
                bu[in][0] = Bs[buf][cu][wu0];
                bu[in][1] = Bs[buf][cu][wu0 ^ 4];
            }
            #pragma unroll
            for (int im = 0; im < 2; ++im) {
                #pragma unroll
                for (int in = 0; in < 4; ++in) {
                    mma_f16(accg[im][in], af[im], bg[in]);
                    mma_f16(accu[im][in], af[im], bu[in]);
                }
            }
        }

        if (kt + 1 < nT) {
            const int nb = (kt + 1) & 1;
            #pragma unroll
            for (int i = 0; i < 2; ++i) {
                const int row = a_row0 + i * 64;
                As[nb][row][a_u * 2 + 0] = pack_h2(ra[i].x, ra[i].y);
                As[nb][row][a_u * 2 + 1] = pack_h2(ra[i].z, ra[i].w);
            }
            #pragma unroll
            for (int i = 0; i < 2; ++i) {
                const int idx = tid + i * 256;
                const int n = idx & 127, kq = idx >> 7;
                const uint32_t w0 = pack_h2(rbx[i][0], rbx[i][1]);
                const uint32_t w1 = pack_h2(rbx[i][2], rbx[i][3]);
                const int woff = (2 * kq) ^ (((n >> 3) & 3) << 1);
                *(uint2*)&Bs[nb][n][woff] = make_uint2(w0, w1);
            }
        }
        __syncthreads();
    }

    // Epilogue: gated = up * silu(gate) -> g_act
    float* Gout = g_act + (size_t)e * TOKENS * EXPERT_DIM;
    #pragma unroll
    for (int im = 0; im < 2; ++im) {
        #pragma unroll
        for (int in = 0; in < 4; ++in) {
            #pragma unroll
            for (int h = 0; h < 2; ++h) {
                const int r = m0 + wm + im * 16 + g + h * 8;
                const int c = n0 + wn + in * 8 + 2 * tg;
                const float gv0 = accg[im][in][h * 2 + 0];
                const float gv1 = accg[im][in][h * 2 + 1];
                const float uv0 = accu[im][in][h * 2 + 0];
                const float uv1 = accu[im][in][h * 2 + 1];
                const float s0 = gv0 / (1.0f + __expf(-gv0));
                const float s1 = gv1 / (1.0f + __expf(-gv1));
                *(float2*)(Gout + (size_t)r * EXPERT_DIM + c) = make_float2(uv0 * s0, uv1 * s1);
            }
        }
    }
}

// ---------------------------------------------------------------------------
// GEMM2: Out[e] = G[e] (1024x4096) @ W2[e] (4096x2048).
// Block: 128 x 128, BK = 16. 8 warps = 2(M) x 4(N). Warp tile 64 x 32.
// 2 CTAs / SM.
// ---------------------------------------------------------------------------
__global__ __launch_bounds__(256, 2) void gemm2_kernel(
    const float* __restrict__ W2,   // [E, I, H]
    float* __restrict__ Out)        // [E*T, H]
{
    __shared__ uint32_t As[2][128][A_ST];
    __shared__ uint32_t Bs[2][128][B_ST];

    const int e  = blockIdx.z;
    const int m0 = blockIdx.y * 128;
    const int n0 = blockIdx.x * 128;

    const int tid  = threadIdx.x;
    const int warp = tid >> 5;
    const int lane = tid & 31;
    const int wm = (warp >> 2) * 64;   // 2 warps in M
    const int wn = (warp & 3) * 32;    // 4 warps in N
    const int g  = lane >> 2;
    const int tg = lane & 3;

    const float* Ap = g_act + (size_t)e * TOKENS * EXPERT_DIM + (size_t)m0 * EXPERT_DIM;
    const float* Bp = W2 + (size_t)e * EXPERT_DIM * HIDDEN + n0;
    const int LDB = HIDDEN;

    const int a_row0 = tid >> 2;
    const int a_u    = tid & 3;

    float4 ra[2];
    float rbx[2][4];

    {
        #pragma unroll
        for (int i = 0; i < 2; ++i) {
            const int row = a_row0 + i * 64;
            float4 v = *(const float4*)(Ap + (size_t)row * EXPERT_DIM + a_u * 4);
            As[0][row][a_u * 2 + 0] = pack_h2(v.x, v.y);
            As[0][row][a_u * 2 + 1] = pack_h2(v.z, v.w);
        }
        #pragma unroll
        for (int i = 0; i < 2; ++i) {
            const int idx = tid + i * 256;
            const int n = idx & 127, kq = idx >> 7;
            const float* p = Bp + (size_t)(kq * 4) * LDB + n;
            const uint32_t w0 = pack_h2(p[0], p[LDB]);
            const uint32_t w1 = pack_h2(p[2 * LDB], p[3 * LDB]);
            const int woff = (2 * kq) ^ (((n >> 3) & 3) << 1);
            *(uint2*)&Bs[0][n][woff] = make_uint2(w0, w1);
        }
    }
    __syncthreads();

    float acc[4][4][4] = {};

    const int nT = EXPERT_DIM / 16;  // 256
    #pragma unroll 1
    for (int kt = 0; kt < nT; ++kt) {
        const int buf = kt & 1;
        if (kt + 1 < nT) {
            const float* a = Ap + (kt + 1) * 16;
            #pragma unroll
            for (int i = 0; i < 2; ++i)
                ra[i] = *(const float4*)(a + (size_t)(a_row0 + i * 64) * EXPERT_DIM + a_u * 4);
            #pragma unroll
            for (int i = 0; i < 2; ++i) {
                const int idx = tid + i * 256;
                const int n = idx & 127, kq = idx >> 7;
                const float* p = Bp + (size_t)((kt + 1) * 16 + kq * 4) * LDB + n;
                rbx[i][0] = p[0];
                rbx[i][1] = p[LDB];
                rbx[i][2] = p[2 * LDB];
                rbx[i][3] = p[3 * LDB];
            }
        }

        {
            uint32_t af[4][4];
            #pragma unroll
            for (int im = 0; im < 4; ++im) {
                const int r = wm + im * 16 + g;
                af[im][0] = As[buf][r][tg];
                af[im][1] = As[buf][r + 8][tg];
                af[im][2] = As[buf][r][tg + 4];
                af[im][3] = As[buf][r + 8][tg + 4];
            }
            uint32_t bf[4][2];
            #pragma unroll
            for (int in = 0; in < 4; ++in) {
                const int c = wn + in * 8 + g;
                const int w0 = tg ^ (((c >> 3) & 3) << 1);
                bf[in][0] = Bs[buf][c][w0];
                bf[in][1] = Bs[buf][c][w0 ^ 4];
            }
            #pragma unroll
            for (int im = 0; im < 4; ++im) {
                #pragma unroll
                for (int in = 0; in < 4; ++in) {
                    mma_f16(acc[im][in], af[im], bf[in]);
                }
            }
        }

        if (kt + 1 < nT) {
            const int nb = (kt + 1) & 1;
            #pragma unroll
            for (int i = 0; i < 2; ++i) {
                const int row = a_row0 + i * 64;
                As[nb][row][a_u * 2 + 0] = pack_h2(ra[i].x, ra[i].y);
                As[nb][row][a_u * 2 + 1] = pack_h2(ra[i].z, ra[i].w);
            }
            #pragma unroll
            for (int i = 0; i < 2; ++i) {
                const int idx = tid + i * 256;
                const int n = idx & 127, kq = idx >> 7;
                const uint32_t w0 = pack_h2(rbx[i][0], rbx[i][1]);
                const uint32_t w1 = pack_h2(rbx[i][2], rbx[i][3]);
                const int woff = (2 * kq) ^ (((n >> 3) & 3) << 1);
                *(uint2*)&Bs[nb][n][woff] = make_uint2(w0, w1);
            }
        }
        __syncthreads();
    }

    float* Optr = Out + (size_t)(e * TOKENS + m0) * HIDDEN + n0;
    #pragma unroll
    for (int im = 0; im < 4; ++im) {
        #pragma unroll
        for (int in = 0; in < 4; ++in) {
            #pragma unroll
            for (int h = 0; h < 2; ++h) {
                const int r = wm + im * 16 + g + h * 8;
                const int c = wn + in * 8 + 2 * tg;
                *(float2*)(Optr + (size_t)r * HIDDEN + c) =
                    make_float2(acc[im][in][h * 2 + 0], acc[im][in][h * 2 + 1]);
            }
        }
    }
}

extern "C" void kernel_launch(void* const* d_in, const int* in_sizes, int n_in,
                              void* d_out, int out_size) {
    const float* X  = (const float*)d_in[0];   // hidden_states [8192, 2048]
    const float* W1 = (const float*)d_in[1];   // gate_up_proj  [8, 2048, 8192]
    const float* W2 = (const float*)d_in[2];   // down_proj     [8, 4096, 2048]
    float* Out = (float*)d_out;                // [8192, 2048]

    dim3 blk(256);
    dim3 g1(EXPERT_DIM / 64, TOKENS / 128, NUM_EXPERTS);   // 64 x 8 x 8
    dim3 g2(HIDDEN / 128, TOKENS / 128, NUM_EXPERTS);      // 16 x 8 x 8
    gemm1_kernel<<<g1, blk>>>(X, W1);
    gemm2_kernel<<<g2, blk>>>(W2, Out);
}

// round 11
// speedup vs baseline: 1.3923x; 1.0000x over previous
#include <cuda_runtime.h>
#include <cstdint>

#define NUM_EXPERTS 8
#define HIDDEN 2048
#define EXPERT_DIM 4096
#define TOKENS 1024

// Gated activations scratch [E, T, I] as fp16x2 words (i/2 words per row)
__device__ uint32_t Gh32[(size_t)NUM_EXPERTS * TOKENS * (EXPERT_DIM / 2)];

// pack two fp32 -> one fp16x2 word: lo = a (even k), hi = b (odd k)
__device__ __forceinline__ uint32_t pack_h2(float a, float b) {
    uint32_t r;
    asm("cvt.rn.f16x2.f32 %0, %1, %2;" : "=r"(r) : "f"(b), "f"(a));
    return r;
}

// D += A*B, m16n8k16 fp16 operands, fp32 accumulate
__device__ __forceinline__ void mma_f16(float* c, const uint32_t* a, const uint32_t* b) {
    asm volatile(
        "mma.sync.aligned.m16n8k16.row.col.f32.f16.f16.f32 "
        "{%0,%1,%2,%3}, {%4,%5,%6,%7}, {%8,%9}, {%0,%1,%2,%3};\n"
        : "+f"(c[0]), "+f"(c[1]), "+f"(c[2]), "+f"(c[3])
        : "r"(a[0]), "r"(a[1]), "r"(a[2]), "r"(a[3]), "r"(b[0]), "r"(b[1]));
}

// Strides in 32-bit words; both ≡ 12 (mod 32) -> fragment loads across
// (g, tg) hit 32 distinct banks (proven rounds 4-5).
#define A_ST 12   // As[row][k-pair word 0..7 (+pad)]
#define B_ST 12   // Bs[n][k-pair word, XOR-swizzled]

// ---------------------------------------------------------------------------
// GEMM1 + silu. Block: 128 tokens x 64 gated cols (gate+up = 128 B rows).
// K = 2048, BK = 16. 8 warps = 4(M) x 2(N). Warp tile 32 x 32 dual.
// 2 CTAs / SM.  (Byte-identical to round 5 except the fp16 epilogue store.)
// ---------------------------------------------------------------------------
__global__ __launch_bounds__(256, 2) void gemm1_kernel(
    const float* __restrict__ X,    // [E*T, H]
    const float* __restrict__ W1)   // [E, H, 2I]
{
    __shared__ uint32_t As[2][128][A_ST];
    __shared__ uint32_t Bs[2][128][B_ST];

    const int e  = blockIdx.z;
    const int m0 = blockIdx.y * 128;
    const int n0 = blockIdx.x * 64;

    const int tid  = threadIdx.x;
    const int warp = tid >> 5;
    const int lane = tid & 31;
    const int wm = (warp >> 1) * 32;   // 4 warps in M
    const int wn = (warp & 1) * 32;    // 2 warps in N
    const int g  = lane >> 2;
    const int tg = lane & 3;

    const float* Ap = X + (size_t)(e * TOKENS + m0) * HIDDEN;
    const float* Bp = W1 + (size_t)e * HIDDEN * (2 * EXPERT_DIM);
    const int LDB = 2 * EXPERT_DIM;

    const int a_row0 = tid >> 2;       // 0..63 (+64)
    const int a_u    = tid & 3;        // float4 index in k16 row

    float4 ra[2];
    float rbx[2][4];

    // prologue
    {
        #pragma unroll
        for (int i = 0; i < 2; ++i) {
            const int row = a_row0 + i * 64;
            float4 v = *(const float4*)(Ap + (size_t)row * HIDDEN + a_u * 4);
            As[0][row][a_u * 2 + 0] = pack_h2(v.x, v.y);
            As[0][row][a_u * 2 + 1] = pack_h2(v.z, v.w);
        }
        #pragma unroll
        for (int i = 0; i < 2; ++i) {
            const int idx = tid + i * 256;       // 0..511
            const int n = idx & 127, kq = idx >> 7;
            const int gcol = n0 + (n < 64 ? n : 4096 + (n - 64));
            const float* p = Bp + (size_t)(kq * 4) * LDB + gcol;
            const uint32_t w0 = pack_h2(p[0], p[LDB]);
            const uint32_t w1 = pack_h2(p[2 * LDB], p[3 * LDB]);
            const int woff = (2 * kq) ^ (((n >> 3) & 3) << 1);
            *(uint2*)&Bs[0][n][woff] = make_uint2(w0, w1);
        }
    }
    __syncthreads();

    float accg[2][4][4] = {};
    float accu[2][4][4] = {};

    const int nT = HIDDEN / 16;  // 128
    #pragma unroll 1
    for (int kt = 0; kt < nT; ++kt) {
        const int buf = kt & 1;
        if (kt + 1 < nT) {
            const float* a = Ap + (kt + 1) * 16;
            #pragma unroll
            for (int i = 0; i < 2; ++i)
                ra[i] = *(const float4*)(a + (size_t)(a_row0 + i * 64) * HIDDEN + a_u * 4);
            #pragma unroll
            for (int i = 0; i < 2; ++i) {
                const int idx = tid + i * 256;
                const int n = idx & 127, kq = idx >> 7;
                const int gcol = n0 + (n < 64 ? n : 4096 + (n - 64));
                const float* p = Bp + (size_t)((kt + 1) * 16 + kq * 4) * LDB + gcol;
                rbx[i][0] = p[0];
                rbx[i][1] = p[LDB];
                rbx[i][2] = p[2 * LDB];
                rbx[i][3] = p[3 * LDB];
            }
        }

        {
            uint32_t af[2][4];
            #pragma unroll
            for (int im = 0; im < 2; ++im) {
                const int r = wm + im * 16 + g;
                af[im][0] = As[buf][r][tg];
                af[im][1] = As[buf][r + 8][tg];
                af[im][2] = As[buf][r][tg + 4];
                af[im][3] = As[buf][r + 8][tg + 4];
            }
            uint32_t bg[4][2], bu[4][2];
            #pragma unroll
            for (int in = 0; in < 4; ++in) {
                const int cg = wn + in * 8 + g;
                const int cu = cg + 64;
                const int wg0 = tg ^ (((cg >> 3) & 3) << 1);
                const int wu0 = tg ^ (((cu >> 3) & 3) << 1);
                bg[in][0] = Bs[buf][cg][wg0];
                bg[in][1] = Bs[buf][cg][wg0 ^ 4];
                bu[in][0] = Bs[buf][cu][wu0];
                bu[in][1] = Bs[buf][cu][wu0 ^ 4];
            }
            #pragma unroll
            for (int im = 0; im < 2; ++im) {
                #pragma unroll
                for (int in = 0; in < 4; ++in) {
                    mma_f16(accg[im][in], af[im], bg[in]);
                    mma_f16(accu[im][in], af[im], bu[in]);
                }
            }
        }

        if (kt + 1 < nT) {
            const int nb = (kt + 1) & 1;
            #pragma unroll
            for (int i = 0; i < 2; ++i) {
                const int row = a_row0 + i * 64;
                As[nb][row][a_u * 2 + 0] = pack_h2(ra[i].x, ra[i].y);
                As[nb][row][a_u * 2 + 1] = pack_h2(ra[i].z, ra[i].w);
            }
            #pragma unroll
            for (int i = 0; i < 2; ++i) {
                const int idx = tid + i * 256;
                const int n = idx & 127, kq = idx >> 7;
                const uint32_t w0 = pack_h2(rbx[i][0], rbx[i][1]);
                const uint32_t w1 = pack_h2(rbx[i][2], rbx[i][3]);
                const int woff = (2 * kq) ^ (((n >> 3) & 3) << 1);
                *(uint2*)&Bs[nb][n][woff] = make_uint2(w0, w1);
            }
        }
        __syncthreads();
    }

    // Epilogue: gated = up * silu(gate) -> Gh32 (fp16x2 words)
    uint32_t* Gp = Gh32 + (size_t)e * TOKENS * (EXPERT_DIM / 2);
    #pragma unroll
    for (int im = 0; im < 2; ++im) {
        #pragma unroll
        for (int in = 0; in < 4; ++in) {
            #pragma unroll
            for (int h = 0; h < 2; ++h) {
                const int r = m0 + wm + im * 16 + g + h * 8;
                const int c = n0 + wn + in * 8 + 2 * tg;   // even
                const float gv0 = accg[im][in][h * 2 + 0];
                const float gv1 = accg[im][in][h * 2 + 1];
                const float uv0 = accu[im][in][h * 2 + 0];
                const float uv1 = accu[im][in][h * 2 + 1];
                const float s0 = gv0 / (1.0f + __expf(-gv0));
                const float s1 = gv1 / (1.0f + __expf(-gv1));
                Gp[(size_t)r * (EXPERT_DIM / 2) + (c >> 1)] = pack_h2(uv0 * s0, uv1 * s1);
            }
        }
    }
}

// ---------------------------------------------------------------------------
// GEMM2: Out[e] = G[e] (1024x4096 fp16) @ W2[e] (4096x2048 fp32).
// Block: 128 x 128, BK = 16. 8 warps = 2(M) x 4(N). Warp tile 64 x 32.
// 2 CTAs / SM.  (Round 5 verbatim except A loads are fp16x2 words.)
// ---------------------------------------------------------------------------
__global__ __launch_bounds__(256, 2) void gemm2_kernel(
    const float* __restrict__ W2,   // [E, I, H]
    float* __restrict__ Out)        // [E*T, H]
{
    __shared__ uint32_t As[2][128][A_ST];
    __shared__ uint32_t Bs[2][128][B_ST];

    const int e  = blockIdx.z;
    const int m0 = blockIdx.y * 128;
    const int n0 = blockIdx.x * 128;

    const int tid  = threadIdx.x;
    const int warp = tid >> 5;
    const int lane = tid & 31;
    const int wm = (warp >> 2) * 64;   // 2 warps in M
    const int wn = (warp & 3) * 32;    // 4 warps in N
    const int g  = lane >> 2;
    const int tg = lane & 3;

    const uint32_t* Ap = Gh32 + (size_t)e * TOKENS * (EXPERT_DIM / 2)
                       + (size_t)m0 * (EXPERT_DIM / 2);
    const float* Bp = W2 + (size_t)e * EXPERT_DIM * HIDDEN + n0;
    const int LDB = HIDDEN;
    const int LDA = EXPERT_DIM / 2;    // words per row

    const int a_row0 = tid >> 2;
    const int a_u    = tid & 3;

    uint2 ra2[2];
    float rbx[2][4];

    {
        #pragma unroll
        for (int i = 0; i < 2; ++i) {
            const int row = a_row0 + i * 64;
            ra2[i] = *(const uint2*)(Ap + (size_t)row * LDA + a_u * 2);
            *(uint2*)&As[0][row][a_u * 2] = ra2[i];
        }
        #pragma unroll
        for (int i = 0; i < 2; ++i) {
            const int idx = tid + i * 256;
            const int n = idx & 127, kq = idx >> 7;
            const float* p = Bp + (size_t)(kq * 4) * LDB + n;
            const uint32_t w0 = pack_h2(p[0], p[LDB]);
            const uint32_t w1 = pack_h2(p[2 * LDB], p[3 * LDB]);
            const int woff = (2 * kq) ^ (((n >> 3) & 3) << 1);
            *(uint2*)&Bs[0][n][woff] = make_uint2(w0, w1);
        }
    }
    __syncthreads();

    float acc[4][4][4] = {};

    const int nT = EXPERT_DIM / 16;  // 256
    #pragma unroll 1
    for (int kt = 0; kt < nT; ++kt) {
        const int buf = kt & 1;
        if (kt + 1 < nT) {
            #pragma unroll
            for (int i = 0; i < 2; ++i) {
                const int row = a_row0 + i * 64;
                ra2[i] = *(const uint2*)(Ap + (size_t)row * LDA + (kt + 1) * 8 + a_u * 2);
            }
            #pragma unroll
            for (int i = 0; i < 2; ++i) {
                const int idx = tid + i * 256;
                const int n = idx & 127, kq = idx >> 7;
                const float* p = Bp + (size_t)((kt + 1) * 16 + kq * 4) * LDB + n;
                rbx[i][0] = p[0];
                rbx[i][1] = p[LDB];
                rbx[i][2] = p[2 * LDB];
                rbx[i][3] = p[3 * LDB];
            }
        }

        {
            uint32_t af[4][4];
            #pragma unroll
            for (int im = 0; im < 4; ++im) {
                const int r = wm + im * 16 + g;
                af[im][0] = As[buf][r][tg];
                af[im][1] = As[buf][r + 8][tg];
                af[im][2] = As[buf][r][tg + 4];
                af[im][3] = As[buf][r + 8][tg + 4];
            }
            uint32_t bf[4][2];
            #pragma unroll
            for (int in = 0; in < 4; ++in) {
                const int c = wn + in * 8 + g;
                const int w0 = tg ^ (((c >> 3) & 3) << 1);
                bf[in][0] = Bs[buf][c][w0];
                bf[in][1] = Bs[buf][c][w0 ^ 4];
            }
            #pragma unroll
            for (int im = 0; im < 4; ++im) {
                #pragma unroll
                for (int in = 0; in < 4; ++in) {
                    mma_f16(acc[im][in], af[im], bf[in]);
                }
            }
        }

        if (kt + 1 < nT) {
            const int nb = (kt + 1) & 1;
            #pragma unroll
            for (int i = 0; i < 2; ++i) {
                const int row = a_row0 + i * 64;
                *(uint2*)&As[nb][row][a_u * 2] = ra2[i];
            }
            #pragma unroll
            for (int i = 0; i < 2; ++i) {
                const int idx = tid + i * 256;
                const int n = idx & 127, kq = idx >> 7;
                const uint32_t w0 = pack_h2(rbx[i][0], rbx[i][1]);
                const uint32_t w1 = pack_h2(rbx[i][2], rbx[i][3]);
                const int woff = (2 * kq) ^ (((n >> 3) & 3) << 1);
                *(uint2*)&Bs[nb][n][woff] = make_uint2(w0, w1);
            }
        }
        __syncthreads();
    }

    float* Optr = Out + (size_t)(e * TOKENS + m0) * HIDDEN + n0;
    #pragma unroll
    for (int im = 0; im < 4; ++im) {
        #pragma unroll
        for (int in = 0; in < 4; ++in) {
            #pragma unroll
            for (int h = 0; h < 2; ++h) {
                const int r = wm + im * 16 + g + h * 8;
                const int c = wn + in * 8 + 2 * tg;
                *(float2*)(Optr + (size_t)r * HIDDEN + c) =
                    make_float2(acc[im][in][h * 2 + 0], acc[im][in][h * 2 + 1]);
            }
        }
    }
}

extern "C" void kernel_launch(void* const* d_in, const int* in_sizes, int n_in,
                              void* d_out, int out_size) {
    const float* X  = (const float*)d_in[0];   // hidden_states [8192, 2048]
    const float* W1 = (const float*)d_in[1];   // gate_up_proj  [8, 2048, 8192]
    const float* W2 = (const float*)d_in[2];   // down_proj     [8, 4096, 2048]
    float* Out = (float*)d_out;                // [8192, 2048]

    dim3 blk(256);
    dim3 g1(EXPERT_DIM / 64, TOKENS / 128, NUM_EXPERTS);   // 64 x 8 x 8
    dim3 g2(HIDDEN / 128, TOKENS / 128, NUM_EXPERTS);      // 16 x 8 x 8
    gemm1_kernel<<<g1, blk>>>(X, W1);
    gemm2_kernel<<<g2, blk>>>(W2, Out);
}

// round 13
// speedup vs baseline: 1.8206x; 1.3076x over previous
#include <cuda_runtime.h>
#include <cstdint>

#define NUM_EXPERTS 8
#define HIDDEN 2048
#define EXPERT_DIM 4096
#define TOKENS 1024

// Gated activations scratch [E, T, I] as fp16x2 words (proven round 9/11)
__device__ uint32_t Gh32[(size_t)NUM_EXPERTS * TOKENS * (EXPERT_DIM / 2)];

__device__ __forceinline__ uint32_t pack_h2(float a, float b) {
    uint32_t r;
    asm("cvt.rn.f16x2.f32 %0, %1, %2;" : "=r"(r) : "f"(b), "f"(a));
    return r;
}

__device__ __forceinline__ void mma_f16(float* c, const uint32_t* a, const uint32_t* b) {
    asm volatile(
        "mma.sync.aligned.m16n8k16.row.col.f32.f16.f16.f32 "
        "{%0,%1,%2,%3}, {%4,%5,%6,%7}, {%8,%9}, {%0,%1,%2,%3};\n"
        : "+f"(c[0]), "+f"(c[1]), "+f"(c[2]), "+f"(c[3])
        : "r"(a[0]), "r"(a[1]), "r"(a[2]), "r"(a[3]), "r"(b[0]), "r"(b[1]));
}

// Rows of 16 k-pair words (BK=32) padded to 20. 20g mod 32 distinct and ≡0 mod 4
// -> fragment loads across (g, tg) cover 32 banks (same algebra as rounds 4-9).
#define R_ST 20

// ---------------------------------------------------------------------------
// GEMM1 + silu. Block: 128 tokens x 64 gated cols. K=2048, BK=32 (nT=64).
// 8 warps = 4(M) x 2(N). Warp tile 32x32 dual. 2 CTAs/SM.
// B smem rows: n 0..63 = gate (col n0+n), 64..127 = up (col 4096+n0+n-64).
// ---------------------------------------------------------------------------
__global__ __launch_bounds__(256, 2) void gemm1_kernel(
    const float* __restrict__ X,    // [E*T, H]
    const float* __restrict__ W1)   // [E, H, 2I]
{
    __shared__ uint32_t As[2][128][R_ST];
    __shared__ uint32_t Bs[2][128][R_ST];

    const int e  = blockIdx.z;
    const int m0 = blockIdx.y * 128;
    const int n0 = blockIdx.x * 64;

    const int tid  = threadIdx.x;
    const int warp = tid >> 5;
    const int lane = tid & 31;
    const int wm = (warp >> 1) * 32;   // 4 warps in M
    const int wn = (warp & 1) * 32;    // 2 warps in N
    const int g  = lane >> 2;
    const int tg = lane & 3;

    const float* Ap = X + (size_t)(e * TOKENS + m0) * HIDDEN;
    const float* Bp = W1 + (size_t)e * HIDDEN * (2 * EXPERT_DIM);
    const int LDB = 2 * EXPERT_DIM;

    // A staging: 1024 float4 units (128 rows x 8), 4/thread
    //   idx = tid + i*256: row = idx>>3, u = idx&7 (k = u*4..u*4+3)
    const int a_row = tid >> 3;
    const int a_u   = tid & 7;
    // B staging: 1024 units (128 n x 8 kq), 4/thread
    //   idx = tid + i*256: n = idx&127, kq = idx>>7 + ... (see loop)

    float4 ra[4];
    float rbx[4][4];

    // prologue: stage tile 0
    {
        #pragma unroll
        for (int i = 0; i < 4; ++i) {
            const int row = a_row + i * 32;
            float4 v = *(const float4*)(Ap + (size_t)row * HIDDEN + a_u * 4);
            *(uint2*)&As[0][row][a_u * 2] = make_uint2(pack_h2(v.x, v.y), pack_h2(v.z, v.w));
        }
        #pragma unroll
        for (int i = 0; i < 4; ++i) {
            const int idx = tid + i * 256;
            const int n = idx & 127, kq = idx >> 7;   // kq 0..7
            const int gcol = n0 + (n < 64 ? n : 4096 + (n - 64));
            const float* p = Bp + (size_t)(kq * 4) * LDB + gcol;
            const uint32_t w0 = pack_h2(p[0], p[LDB]);
            const uint32_t w1 = pack_h2(p[2 * LDB], p[3 * LDB]);
            const int woff = (kq * 2) ^ (((n >> 3) & 3) << 1);
            *(uint2*)&Bs[0][n][woff] = make_uint2(w0, w1);
        }
    }
    __syncthreads();

    float accg[2][4][4] = {};
    float accu[2][4][4] = {};

    const int nT = HIDDEN / 32;  // 64
    #pragma unroll 1
    for (int kt = 0; kt < nT; ++kt) {
        const int buf = kt & 1;
        if (kt + 1 < nT) {
            const float* a = Ap + (kt + 1) * 32;
            #pragma unroll
            for (int i = 0; i < 4; ++i)
                ra[i] = *(const float4*)(a + (size_t)(a_row + i * 32) * HIDDEN + a_u * 4);
            #pragma unroll
            for (int i = 0; i < 4; ++i) {
                const int idx = tid + i * 256;
                const int n = idx & 127, kq = idx >> 7;
                const int gcol = n0 + (n < 64 ? n : 4096 + (n - 64));
                const float* p = Bp + (size_t)((kt + 1) * 32 + kq * 4) * LDB + gcol;
                rbx[i][0] = p[0];
                rbx[i][1] = p[LDB];
                rbx[i][2] = p[2 * LDB];
                rbx[i][3] = p[3 * LDB];
            }
        }

        #pragma unroll
        for (int ks = 0; ks < 2; ++ks) {
            const int k8 = ks * 8;
            uint32_t af[2][4];
            #pragma unroll
            for (int im = 0; im < 2; ++im) {
                const int r = wm + im * 16 + g;
                af[im][0] = As[buf][r][k8 + tg];
                af[im][1] = As[buf][r + 8][k8 + tg];
                af[im][2] = As[buf][r][k8 + tg + 4];
                af[im][3] = As[buf][r + 8][k8 + tg + 4];
            }
            uint32_t bg[4][2], bu[4][2];
            #pragma unroll
            for (int in = 0; in < 4; ++in) {
                const int cg = wn + in * 8 + g;
                const int cu = cg + 64;
                const int swg = ((cg >> 3) & 3) << 1;
                const int swu = ((cu >> 3) & 3) << 1;
                bg[in][0] = Bs[buf][cg][(k8 + tg) ^ swg];
                bg[in][1] = Bs[buf][cg][(k8 + tg + 4) ^ swg];
                bu[in][0] = Bs[buf][cu][(k8 + tg) ^ swu];
                bu[in][1] = Bs[buf][cu][(k8 + tg + 4) ^ swu];
            }
            #pragma unroll
            for (int im = 0; im < 2; ++im) {
                #pragma unroll
                for (int in = 0; in < 4; ++in) {
                    mma_f16(accg[im][in], af[im], bg[in]);
                    mma_f16(accu[im][in], af[im], bu[in]);
                }
            }
        }

        if (kt + 1 < nT) {
            const int nb = (kt + 1) & 1;
            #pragma unroll
            for (int i = 0; i < 4; ++i) {
                const int row = a_row + i * 32;
                *(uint2*)&As[nb][row][a_u * 2] =
                    make_uint2(pack_h2(ra[i].x, ra[i].y), pack_h2(ra[i].z, ra[i].w));
            }
            #pragma unroll
            for (int i = 0; i < 4; ++i) {
                const int idx = tid + i * 256;
                const int n = idx & 127, kq = idx >> 7;
                const uint32_t w0 = pack_h2(rbx[i][0], rbx[i][1]);
                const uint32_t w1 = pack_h2(rbx[i][2], rbx[i][3]);
                const int woff = (kq * 2) ^ (((n >> 3) & 3) << 1);
                *(uint2*)&Bs[nb][n][woff] = make_uint2(w0, w1);
            }
        }
        __syncthreads();
    }

    // Epilogue: gated = up * silu(gate) -> Gh32 (fp16x2)
    uint32_t* Gp = Gh32 + (size_t)e * TOKENS * (EXPERT_DIM / 2);
    #pragma unroll
    for (int im = 0; im < 2; ++im) {
        #pragma unroll
        for (int in = 0; in < 4; ++in) {
            #pragma unroll
            for (int h = 0; h < 2; ++h) {
                const int r = m0 + wm + im * 16 + g + h * 8;
                const int c = n0 + wn + in * 8 + 2 * tg;
                const float gv0 = accg[im][in][h * 2 + 0];
                const float gv1 = accg[im][in][h * 2 + 1];
                const float uv0 = accu[im][in][h * 2 + 0];
                const float uv1 = accu[im][in][h * 2 + 1];
                const float s0 = gv0 / (1.0f + __expf(-gv0));
                const float s1 = gv1 / (1.0f + __expf(-gv1));
                Gp[(size_t)r * (EXPERT_DIM / 2) + (c >> 1)] = pack_h2(uv0 * s0, uv1 * s1);
            }
        }
    }
}

// ---------------------------------------------------------------------------
// GEMM2: Out[e] = G[e] (1024x4096 fp16) @ W2[e] (4096x2048 fp32).
// Block 128x128, BK=32 (nT=128). 8 warps = 2(M) x 4(N). Warp tile 64x32.
// 2 CTAs/SM.
// ---------------------------------------------------------------------------
__global__ __launch_bounds__(256, 2) void gemm2_kernel(
    const float* __restrict__ W2,   // [E, I, H]
    float* __restrict__ Out)        // [E*T, H]
{
    __shared__ uint32_t As[2][128][R_ST];
    __shared__ uint32_t Bs[2][128][R_ST];

    const int e  = blockIdx.z;
    const int m0 = blockIdx.y * 128;
    const int n0 = blockIdx.x * 128;

    const int tid  = threadIdx.x;
    const int warp = tid >> 5;
    const int lane = tid & 31;
    const int wm = (warp >> 2) * 64;   // 2 warps in M
    const int wn = (warp & 3) * 32;    // 4 warps in N
    const int g  = lane >> 2;
    const int tg = lane & 3;

    const uint32_t* Ap = Gh32 + (size_t)e * TOKENS * (EXPERT_DIM / 2)
                       + (size_t)m0 * (EXPERT_DIM / 2);
    const float* Bp = W2 + (size_t)e * EXPERT_DIM * HIDDEN + n0;
    const int LDB = HIDDEN;
    const int LDA = EXPERT_DIM / 2;    // words per row

    // A staging: 512 uint4 units (128 rows x 4), 2/thread
    //   idx = tid + i*256: row = idx>>2, q = idx&3 (words q*4..q*4+3)
    const int a_row = tid >> 2;
    const int a_q   = tid & 3;

    uint4 ra4[2];
    float rbx[4][4];

    {
        #pragma unroll
        for (int i = 0; i < 2; ++i) {
            const int row = a_row + i * 64;
            ra4[i] = *(const uint4*)(Ap + (size_t)row * LDA + a_q * 4);
            *(uint4*)&As[0][row][a_q * 4] = ra4[i];
        }
        #pragma unroll
        for (int i = 0; i < 4; ++i) {
            const int idx = tid + i * 256;
            const int n = idx & 127, kq = idx >> 7;
            const float* p = Bp + (size_t)(kq * 4) * LDB + n;
            const uint32_t w0 = pack_h2(p[0], p[LDB]);
            const uint32_t w1 = pack_h2(p[2 * LDB], p[3 * LDB]);
            const int woff = (kq * 2) ^ (((n >> 3) & 3) << 1);
            *(uint2*)&Bs[0][n][woff] = make_uint2(w0, w1);
        }
    }
    __syncthreads();

    float acc[4][4][4] = {};

    const int nT = EXPERT_DIM / 32;  // 128
    #pragma unroll 1
    for (int kt = 0; kt < nT; ++kt) {
        const int buf = kt & 1;
        if (kt + 1 < nT) {
            #pragma unroll
            for (int i = 0; i < 2; ++i) {
                const int row = a_row + i * 64;
                ra4[i] = *(const uint4*)(Ap + (size_t)row * LDA + (kt + 1) * 16 + a_q * 4);
            }
            #pragma unroll
            for (int i = 0; i < 4; ++i) {
                const int idx = tid + i * 256;
                const int n = idx & 127, kq = idx >> 7;
                const float* p = Bp + (size_t)((kt + 1) * 32 + kq * 4) * LDB + n;
                rbx[i][0] = p[0];
                rbx[i][1] = p[LDB];
                rbx[i][2] = p[2 * LDB];
                rbx[i][3] = p[3 * LDB];
            }
        }

        #pragma unroll
        for (int ks = 0; ks < 2; ++ks) {
            const int k8 = ks * 8;
            uint32_t af[4][4];
            #pragma unroll
            for (int im = 0; im < 4; ++im) {
                const int r = wm + im * 16 + g;
                af[im][0] = As[buf][r][k8 + tg];
                af[im][1] = As[buf][r + 8][k8 + tg];
                af[im][2] = As[buf][r][k8 + tg + 4];
                af[im][3] = As[buf][r + 8][k8 + tg + 4];
            }
            uint32_t bf[4][2];
            #pragma unroll
            for (int in = 0; in < 4; ++in) {
                const int c = wn + in * 8 + g;
                const int sw = ((c >> 3) & 3) << 1;
                bf[in][0] = Bs[buf][c][(k8 + tg) ^ sw];
                bf[in][1] = Bs[buf][c][(k8 + tg + 4) ^ sw];
            }
            #pragma unroll
            for (int im = 0; im < 4; ++im) {
                #pragma unroll
                for (int in = 0; in < 4; ++in) {
                    mma_f16(acc[im][in], af[im], bf[in]);
                }
            }
        }

        if (kt + 1 < nT) {
            const int nb = (kt + 1) & 1;
            #pragma unroll
            for (int i = 0; i < 2; ++i) {
                const int row = a_row + i * 64;
                *(uint4*)&As[nb][row][a_q * 4] = ra4[i];
            }
            #pragma unroll
            for (int i = 0; i < 4; ++i) {
                const int idx = tid + i * 256;
                const int n = idx & 127, kq = idx >> 7;
                const uint32_t w0 = pack_h2(rbx[i][0], rbx[i][1]);
                const uint32_t w1 = pack_h2(rbx[i][2], rbx[i][3]);
                const int woff = (kq * 2) ^ (((n >> 3) & 3) << 1);
                *(uint2*)&Bs[nb][n][woff] = make_uint2(w0, w1);
            }
        }
        __syncthreads();
    }

    float* Optr = Out + (size_t)(e * TOKENS + m0) * HIDDEN + n0;
    #pragma unroll
    for (int im = 0; im < 4; ++im) {
        #pragma unroll
        for (int in = 0; in < 4; ++in) {
            #pragma unroll
            for (int h = 0; h < 2; ++h) {
                const int r = wm + im * 16 + g + h * 8;
                const int c = wn + in * 8 + 2 * tg;
                *(float2*)(Optr + (size_t)r * HIDDEN + c) =
                    make_float2(acc[im][in][h * 2 + 0], acc[im][in][h * 2 + 1]);
            }
        }
    }
}

extern "C" void kernel_launch(void* const* d_in, const int* in_sizes, int n_in,
                              void* d_out, int out_size) {
    const float* X  = (const float*)d_in[0];   // hidden_states [8192, 2048]
    const float* W1 = (const float*)d_in[1];   // gate_up_proj  [8, 2048, 8192]
    const float* W2 = (const float*)d_in[2];   // down_proj     [8, 4096, 2048]
    float* Out = (float*)d_out;                // [8192, 2048]

    dim3 blk(256);
    dim3 g1(EXPERT_DIM / 64, TOKENS / 128, NUM_EXPERTS);   // 64 x 8 x 8
    dim3 g2(HIDDEN / 128, TOKENS / 128, NUM_EXPERTS);      // 16 x 8 x 8
    gemm1_kernel<<<g1, blk>>>(X, W1);
    gemm2_kernel<<<g2, blk>>>(W2, Out);
}